// round 14
// baseline (speedup 1.0000x reference)
#include <cuda_runtime.h>

#define TPB 512
#define CPB 512          // cells per block
#define MAX_GRID 16384

// SoA per-block partials: [k * grid + bid], k in {nobj_count, reg, conf, noobj, cls}
__device__ float g_partials[5 * MAX_GRID];
__device__ unsigned int g_counter = 0;   // atomicInc wraps back to 0 -> replay-safe

__device__ __forceinline__ void cp_async16(unsigned int saddr, const void* gptr) {
    asm volatile("cp.async.cg.shared.global [%0], [%1], 16;" :: "r"(saddr), "l"(gptr));
}
__device__ __forceinline__ void cp_commit() {
    asm volatile("cp.async.commit_group;" ::: "memory");
}
__device__ __forceinline__ void cp_wait_all() {
    asm volatile("cp.async.wait_group 0;" ::: "memory");
}

__device__ __forceinline__ float iou_pred_vs_tgt(
    float px, float py, float pw, float ph,
    float tx1, float ty1, float tx2, float ty2, float tarea)
{
    const float invS = 1.0f / 14.0f;
    float cx = px * invS, cy = py * invS;
    float x1 = cx - 0.5f * pw, y1 = cy - 0.5f * ph;
    float x2 = cx + 0.5f * pw, y2 = cy + 0.5f * ph;
    float lx = fmaxf(x1, tx1), ly = fmaxf(y1, ty1);
    float rx = fminf(x2, tx2), ry = fminf(y2, ty2);
    float wx = fmaxf(rx - lx, 0.0f), wy = fmaxf(ry - ly, 0.0f);
    float inter = wx * wy;
    float a1 = (x2 - x1) * (y2 - y1);
    return inter / (a1 + tarea - inter);
}

__global__ void __launch_bounds__(TPB, 3)
yolo_fused_kernel(const float* __restrict__ pred,
                  const float* __restrict__ tbox,
                  const float* __restrict__ tcls,
                  const void* __restrict__ objmap,
                  int n_cells, float n_batch, float* __restrict__ out)
{
    __shared__ float s_pred[CPB * 30];        // 60 KB, mirrors gmem layout
    __shared__ float s_red[5 * (TPB / 32)];
    __shared__ double s_dred[TPB / 32];
    __shared__ double s_tot[5];
    __shared__ int s_last;

    const int tid  = threadIdx.x;
    const int lane = tid & 31;
    const int warp = tid >> 5;
    const int bid  = blockIdx.x;
    const int grid = gridDim.x;
    const int cellbase = bid * CPB;
    int cib = n_cells - cellbase;
    if (cib > CPB) cib = CPB;

    // ---- dtype detection: single fused block-OR over the SAME first 2KB ----
    unsigned int wdet = ((const unsigned int*)objmap)[tid];
    int mybits = (wdet == 0x3F800000u) ? 2 : ((wdet > 1u) ? 1 : 0);
    int bits = __syncthreads_or(mybits);
    const int flag = (bits & 2) ? 2 : ((bits & 1) ? 0 : 1);  // 2=f32, 0=bool bytes, 1=int32

    // ---- Phase A1: stage pred tile to SMEM via cp.async (reg-free, L1-bypass) ----
    if (cib == CPB) {
        const float4* pred4 = reinterpret_cast<const float4*>(pred + (size_t)cellbase * 30);
        unsigned int sbase = (unsigned int)__cvta_generic_to_shared(&s_pred[0]);
        #pragma unroll
        for (int k = 0; k < 8; k++) {
            int i = tid + k * TPB;
            if (i < (CPB * 30) / 4) cp_async16(sbase + (unsigned)i * 16u, pred4 + i);
        }
    } else {
        const float* predb = pred + (size_t)cellbase * 30;
        for (int i = tid; i < cib * 30; i += TPB) s_pred[i] = predb[i];
    }
    cp_commit();

    // ---- obj + predicated tbox prefetch (independent of cp.async) ----
    float o_mine = 0.0f;
    if (tid < cib) {
        int idx = cellbase + tid;
        if (flag == 2)      o_mine = ((const float*)objmap)[idx];
        else if (flag == 1) o_mine = (((const int*)objmap)[idx] != 0) ? 1.0f : 0.0f;
        else                o_mine = ((const unsigned char*)objmap)[idx] ? 1.0f : 0.0f;
    }
    float4 tb = make_float4(0.f, 0.f, 0.f, 0.f);
    if (tid < cib && o_mine > 0.0f)
        tb = reinterpret_cast<const float4*>(tbox)[cellbase + tid];

    cp_wait_all();
    __syncthreads();

    // ---- Unified per-cell phase: thread == cell for EVERYTHING ----
    float acc_cls = 0.0f, acc_reg = 0.0f, acc_conf = 0.0f, acc_nobjcnt = 0.0f, acc_noobj = 0.0f;
    if (tid < cib) {
        const float obj = o_mine;
        acc_nobjcnt = obj;

        const float* bb = &s_pred[tid * 30];
        float2 p01 = *reinterpret_cast<const float2*>(bb + 0);
        float2 p23 = *reinterpret_cast<const float2*>(bb + 2);
        float2 p45 = *reinterpret_cast<const float2*>(bb + 4);
        float2 p67 = *reinterpret_cast<const float2*>(bb + 6);
        float2 p89 = *reinterpret_cast<const float2*>(bb + 8);
        float b1x = p01.x, b1y = p01.y, b1w = p23.x, b1h = p23.y, b1c = p45.x;
        float b2x = p45.y, b2y = p67.x, b2w = p67.y, b2h = p89.x, b2c = p89.y;

        float sq = b1x * b1x + b1y * b1y + b1w * b1w + b1h * b1h + b1c * b1c
                 + b2x * b2x + b2y * b2y + b2w * b2w + b2h * b2h + b2c * b2c;
        acc_noobj = (1.0f - obj) * sq;

        if (obj > 0.0f) {
            // ---- cls: 20 pred values from SMEM vs 5 tcls float4 from gmem ----
            const float4* tcls4 = reinterpret_cast<const float4*>(tcls) + (size_t)(cellbase + tid) * 5;
            float csum = 0.0f;
            #pragma unroll
            for (int k = 0; k < 5; k++) {
                float4 t = tcls4[k];
                float2 a = *reinterpret_cast<const float2*>(bb + 10 + 4 * k);
                float2 b = *reinterpret_cast<const float2*>(bb + 12 + 4 * k);
                float d0 = a.x - t.x, d1 = a.y - t.y;
                float d2 = b.x - t.z, d3 = b.y - t.w;
                csum += d0 * d0 + d1 * d1 + d2 * d2 + d3 * d3;
            }
            acc_cls = obj * csum;

            // ---- IoU / reg / conf ----
            const float invS = 1.0f / 14.0f;
            float tcx = tb.x * invS, tcy = tb.y * invS;
            float tx1 = tcx - 0.5f * tb.z, ty1 = tcy - 0.5f * tb.w;
            float tx2 = tcx + 0.5f * tb.z, ty2 = tcy + 0.5f * tb.w;
            float tarea = (tx2 - tx1) * (ty2 - ty1);

            float iou1 = iou_pred_vs_tgt(b1x, b1y, b1w, b1h, tx1, ty1, tx2, ty2, tarea);
            float iou2 = iou_pred_vs_tgt(b2x, b2y, b2w, b2h, tx1, ty1, tx2, ty2, tarea);

            bool take1 = (iou1 >= iou2);
            float bx = take1 ? b1x : b2x;
            float by = take1 ? b1y : b2y;
            float bw = take1 ? b1w : b2w;
            float bh = take1 ? b1h : b2h;
            float bc = take1 ? b1c : b2c;
            float biou = take1 ? iou1 : iou2;

            float dx = bx - tb.x;
            float dy = by - tb.y;
            float dw = sqrtf(bw) - sqrtf(tb.z);
            float dh = sqrtf(bh) - sqrtf(tb.w);
            acc_reg = dx * dx + dy * dy + dw * dw + dh * dh;

            float dc = bc - biou;
            acc_conf = dc * dc;
        }
    }

    // ---- Block reduction of 5 accumulators -> SoA partials ----
    float vals[5] = {acc_nobjcnt, acc_reg, acc_conf, acc_noobj, acc_cls};
    #pragma unroll
    for (int k = 0; k < 5; k++) {
        float v = vals[k];
        #pragma unroll
        for (int off = 16; off > 0; off >>= 1)
            v += __shfl_down_sync(0xffffffffu, v, off);
        if (lane == 0) s_red[k * (TPB / 32) + warp] = v;
    }
    __syncthreads();
    if (tid < 5) {
        float v = 0.0f;
        #pragma unroll
        for (int w2 = 0; w2 < TPB / 32; w2++)
            v += s_red[tid * (TPB / 32) + w2];
        g_partials[tid * grid + bid] = v;
    }

    // ---- Last-block finalize ----
    if (tid == 0) {
        __threadfence();
        unsigned int old = atomicInc(&g_counter, (unsigned int)(grid - 1));
        s_last = (old == (unsigned int)(grid - 1)) ? 1 : 0;
    }
    __syncthreads();
    if (!s_last) return;
    __threadfence();   // acquire: order partial reads after the counter observation

    double acc[5] = {0.0, 0.0, 0.0, 0.0, 0.0};
    for (int i = tid; i < grid; i += TPB) {
        #pragma unroll
        for (int k = 0; k < 5; k++)
            acc[k] += (double)g_partials[k * grid + i];
    }
    #pragma unroll
    for (int k = 0; k < 5; k++) {
        double v = acc[k];
        #pragma unroll
        for (int off = 16; off > 0; off >>= 1)
            v += __shfl_down_sync(0xffffffffu, v, off);
        if (lane == 0) s_dred[warp] = v;
        __syncthreads();
        if (tid == 0) {
            double tsum = 0.0;
            #pragma unroll
            for (int w2 = 0; w2 < TPB / 32; w2++) tsum += s_dred[w2];
            s_tot[k] = tsum;
        }
        __syncthreads();
    }

    if (tid == 0) {
        double n_obj   = s_tot[0];
        double n_noobj = (double)n_cells - n_obj;
        double reg_loss   = 5.0 * s_tot[1] / n_obj;
        double conf_loss  = s_tot[2] / n_obj;
        double noobj_loss = 0.5 * s_tot[3] / n_noobj;
        double cls_loss   = s_tot[4] / (double)n_batch;
        double total = reg_loss + conf_loss + noobj_loss + cls_loss;
        out[0] = (float)total;
        out[1] = (float)reg_loss;
        out[2] = (float)conf_loss;
        out[3] = (float)noobj_loss;
        out[4] = (float)cls_loss;
    }
}

extern "C" void kernel_launch(void* const* d_in, const int* in_sizes, int n_in,
                              void* d_out, int out_size)
{
    const float* pred = (const float*)d_in[0];
    const float* tbox = (const float*)d_in[1];
    const float* tcls = (const float*)d_in[2];
    const void*  objmap = d_in[3];
    float* out = (float*)d_out;

    const int n_cells = in_sizes[3];                  // N * S * S
    const int n_batch = in_sizes[0] / (14 * 14 * 30);
    int grid = (n_cells + CPB - 1) / CPB;
    if (grid > MAX_GRID) grid = MAX_GRID;             // not reachable at this shape

    yolo_fused_kernel<<<grid, TPB>>>(pred, tbox, tcls, objmap,
                                     n_cells, (float)n_batch, out);
}

// round 15
// speedup vs baseline: 1.0381x; 1.0381x over previous
#include <cuda_runtime.h>

#define TPB 512
#define CPB 512          // cells per block
#define MAX_GRID 16384

// SoA per-block partials: [k * grid + bid], k in {nobj_count, reg, conf, noobj, cls}
__device__ float g_partials[5 * MAX_GRID];
__device__ unsigned int g_counter = 0;   // atomicInc wraps back to 0 -> replay-safe

__device__ __forceinline__ void cp_async16(unsigned int saddr, const void* gptr) {
    asm volatile("cp.async.cg.shared.global [%0], [%1], 16;" :: "r"(saddr), "l"(gptr));
}
__device__ __forceinline__ void cp_commit() {
    asm volatile("cp.async.commit_group;" ::: "memory");
}
__device__ __forceinline__ void cp_wait_all() {
    asm volatile("cp.async.wait_group 0;" ::: "memory");
}

__device__ __forceinline__ float iou_pred_vs_tgt(
    float px, float py, float pw, float ph,
    float tx1, float ty1, float tx2, float ty2, float tarea)
{
    const float invS = 1.0f / 14.0f;
    float cx = px * invS, cy = py * invS;
    float x1 = cx - 0.5f * pw, y1 = cy - 0.5f * ph;
    float x2 = cx + 0.5f * pw, y2 = cy + 0.5f * ph;
    float lx = fmaxf(x1, tx1), ly = fmaxf(y1, ty1);
    float rx = fminf(x2, tx2), ry = fminf(y2, ty2);
    float wx = fmaxf(rx - lx, 0.0f), wy = fmaxf(ry - ly, 0.0f);
    float inter = wx * wy;
    float a1 = (x2 - x1) * (y2 - y1);
    return inter / (a1 + tarea - inter);
}

__global__ void __launch_bounds__(TPB, 3)
yolo_fused_kernel(const float* __restrict__ pred,
                  const float* __restrict__ tbox,
                  const float* __restrict__ tcls,
                  const void* __restrict__ objmap,
                  int n_cells, float n_batch, float* __restrict__ out)
{
    __shared__ float s_pred[CPB * 30];        // 60 KB, mirrors gmem layout
    __shared__ float s_obj[CPB];
    __shared__ float s_red[5 * (TPB / 32)];
    __shared__ double s_dred[TPB / 32];
    __shared__ double s_tot[5];
    __shared__ int s_last;

    const int tid  = threadIdx.x;
    const int lane = tid & 31;
    const int warp = tid >> 5;
    const int bid  = blockIdx.x;
    const int grid = gridDim.x;
    const int cellbase = bid * CPB;
    int cib = n_cells - cellbase;
    if (cib > CPB) cib = CPB;

    // ---- dtype detection: single fused block-OR over the SAME first 2KB ----
    unsigned int wdet = ((const unsigned int*)objmap)[tid];
    int mybits = (wdet == 0x3F800000u) ? 2 : ((wdet > 1u) ? 1 : 0);
    int bits = __syncthreads_or(mybits);
    const int flag = (bits & 2) ? 2 : ((bits & 1) ? 0 : 1);  // 2=f32, 0=bool bytes, 1=int32

    // ---- Phase A1: stage pred tile to SMEM via cp.async (reg-free, L1-bypass) ----
    if (cib == CPB) {
        const float4* pred4 = reinterpret_cast<const float4*>(pred + (size_t)cellbase * 30);
        unsigned int sbase = (unsigned int)__cvta_generic_to_shared(&s_pred[0]);
        #pragma unroll
        for (int k = 0; k < 8; k++) {
            int i = tid + k * TPB;
            if (i < (CPB * 30) / 4) cp_async16(sbase + (unsigned)i * 16u, pred4 + i);
        }
    } else {
        const float* predb = pred + (size_t)cellbase * 30;
        for (int i = tid; i < cib * 30; i += TPB) s_pred[i] = predb[i];
    }
    cp_commit();

    // ---- obj map + predicated tbox prefetch (independent of cp.async) ----
    float o_mine = 0.0f;
    if (tid < cib) {
        int idx = cellbase + tid;
        if (flag == 2)      o_mine = ((const float*)objmap)[idx];
        else if (flag == 1) o_mine = (((const int*)objmap)[idx] != 0) ? 1.0f : 0.0f;
        else                o_mine = ((const unsigned char*)objmap)[idx] ? 1.0f : 0.0f;
        s_obj[tid] = o_mine;
    }
    float4 tb = make_float4(0.f, 0.f, 0.f, 0.f);
    if (tid < cib && o_mine > 0.0f)
        tb = reinterpret_cast<const float4*>(tbox)[cellbase + tid];

    cp_wait_all();
    __syncthreads();

    // ---- Phase A2: cls loop; tcls as predicated float4 (5 f4 per cell, coalesced) ----
    float acc_cls = 0.0f;
    const float4* tcls4 = reinterpret_cast<const float4*>(tcls + (size_t)cellbase * 20);
    if (cib == CPB) {
        int cell = tid / 5;
        int r = tid - cell * 5;           // cls f4 index within cell (0..4)
        #pragma unroll
        for (int k = 0; k < 5; k++) {
            int i = tid + k * TPB;        // == cell*5 + r  (contiguous across the warp)
            float obj = s_obj[cell];
            float4 t = make_float4(0.f, 0.f, 0.f, 0.f);
            if (obj > 0.0f) t = tcls4[i];             // @P LDG.128
            const float* pp = &s_pred[cell * 30 + 10 + 4 * r];
            float2 a = *reinterpret_cast<const float2*>(pp);
            float2 b = *reinterpret_cast<const float2*>(pp + 2);
            float d0 = a.x - t.x, d1 = a.y - t.y;
            float d2 = b.x - t.z, d3 = b.y - t.w;
            acc_cls += obj * (d0 * d0 + d1 * d1 + d2 * d2 + d3 * d3);
            cell += 102; r += 2;
            if (r >= 5) { r -= 5; ++cell; }           // 512 = 102*5 + 2
        }
    } else {
        for (int i = tid; i < cib * 5; i += TPB) {
            int cell = i / 5;
            int r = i - cell * 5;
            float obj = s_obj[cell];
            float4 t = make_float4(0.f, 0.f, 0.f, 0.f);
            if (obj > 0.0f) t = tcls4[i];
            const float* pp = &s_pred[cell * 30 + 10 + 4 * r];
            float2 a = *reinterpret_cast<const float2*>(pp);
            float2 b = *reinterpret_cast<const float2*>(pp + 2);
            float d0 = a.x - t.x, d1 = a.y - t.y;
            float d2 = b.x - t.z, d3 = b.y - t.w;
            acc_cls += obj * (d0 * d0 + d1 * d1 + d2 * d2 + d3 * d3);
        }
    }

    // ---- Phase B: per-cell noobj squares + IoU/reg/conf from SMEM (float2 reads) ----
    float acc_reg = 0.0f, acc_conf = 0.0f, acc_nobjcnt = 0.0f, acc_noobj = 0.0f;
    if (tid < cib) {
        float obj = o_mine;
        acc_nobjcnt = obj;

        const float* bb = &s_pred[tid * 30];
        float2 p01 = *reinterpret_cast<const float2*>(bb + 0);
        float2 p23 = *reinterpret_cast<const float2*>(bb + 2);
        float2 p45 = *reinterpret_cast<const float2*>(bb + 4);
        float2 p67 = *reinterpret_cast<const float2*>(bb + 6);
        float2 p89 = *reinterpret_cast<const float2*>(bb + 8);
        float b1x = p01.x, b1y = p01.y, b1w = p23.x, b1h = p23.y, b1c = p45.x;
        float b2x = p45.y, b2y = p67.x, b2w = p67.y, b2h = p89.x, b2c = p89.y;

        float sq = b1x * b1x + b1y * b1y + b1w * b1w + b1h * b1h + b1c * b1c
                 + b2x * b2x + b2y * b2y + b2w * b2w + b2h * b2h + b2c * b2c;
        acc_noobj = (1.0f - obj) * sq;

        if (obj > 0.0f) {
            const float invS = 1.0f / 14.0f;
            float tcx = tb.x * invS, tcy = tb.y * invS;
            float tx1 = tcx - 0.5f * tb.z, ty1 = tcy - 0.5f * tb.w;
            float tx2 = tcx + 0.5f * tb.z, ty2 = tcy + 0.5f * tb.w;
            float tarea = (tx2 - tx1) * (ty2 - ty1);

            float iou1 = iou_pred_vs_tgt(b1x, b1y, b1w, b1h, tx1, ty1, tx2, ty2, tarea);
            float iou2 = iou_pred_vs_tgt(b2x, b2y, b2w, b2h, tx1, ty1, tx2, ty2, tarea);

            bool take1 = (iou1 >= iou2);
            float bx = take1 ? b1x : b2x;
            float by = take1 ? b1y : b2y;
            float bw = take1 ? b1w : b2w;
            float bh = take1 ? b1h : b2h;
            float bc = take1 ? b1c : b2c;
            float biou = take1 ? iou1 : iou2;

            float dx = bx - tb.x;
            float dy = by - tb.y;
            float dw = sqrtf(bw) - sqrtf(tb.z);
            float dh = sqrtf(bh) - sqrtf(tb.w);
            acc_reg = dx * dx + dy * dy + dw * dw + dh * dh;

            float dc = bc - biou;
            acc_conf = dc * dc;
        }
    }

    // ---- Block reduction of 5 accumulators -> SoA partials ----
    float vals[5] = {acc_nobjcnt, acc_reg, acc_conf, acc_noobj, acc_cls};
    #pragma unroll
    for (int k = 0; k < 5; k++) {
        float v = vals[k];
        #pragma unroll
        for (int off = 16; off > 0; off >>= 1)
            v += __shfl_down_sync(0xffffffffu, v, off);
        if (lane == 0) s_red[k * (TPB / 32) + warp] = v;
    }
    __syncthreads();
    if (tid < 5) {
        float v = 0.0f;
        #pragma unroll
        for (int w2 = 0; w2 < TPB / 32; w2++)
            v += s_red[tid * (TPB / 32) + w2];
        g_partials[tid * grid + bid] = v;
    }

    // ---- Last-block finalize ----
    if (tid == 0) {
        __threadfence();
        unsigned int old = atomicInc(&g_counter, (unsigned int)(grid - 1));
        s_last = (old == (unsigned int)(grid - 1)) ? 1 : 0;
    }
    __syncthreads();
    if (!s_last) return;
    __threadfence();   // acquire: order partial reads after the counter observation

    double acc[5] = {0.0, 0.0, 0.0, 0.0, 0.0};
    for (int i = tid; i < grid; i += TPB) {
        #pragma unroll
        for (int k = 0; k < 5; k++)
            acc[k] += (double)g_partials[k * grid + i];
    }
    #pragma unroll
    for (int k = 0; k < 5; k++) {
        double v = acc[k];
        #pragma unroll
        for (int off = 16; off > 0; off >>= 1)
            v += __shfl_down_sync(0xffffffffu, v, off);
        if (lane == 0) s_dred[warp] = v;
        __syncthreads();
        if (tid == 0) {
            double tsum = 0.0;
            #pragma unroll
            for (int w2 = 0; w2 < TPB / 32; w2++) tsum += s_dred[w2];
            s_tot[k] = tsum;
        }
        __syncthreads();
    }

    if (tid == 0) {
        double n_obj   = s_tot[0];
        double n_noobj = (double)n_cells - n_obj;
        double reg_loss   = 5.0 * s_tot[1] / n_obj;
        double conf_loss  = s_tot[2] / n_obj;
        double noobj_loss = 0.5 * s_tot[3] / n_noobj;
        double cls_loss   = s_tot[4] / (double)n_batch;
        double total = reg_loss + conf_loss + noobj_loss + cls_loss;
        out[0] = (float)total;
        out[1] = (float)reg_loss;
        out[2] = (float)conf_loss;
        out[3] = (float)noobj_loss;
        out[4] = (float)cls_loss;
    }
}

extern "C" void kernel_launch(void* const* d_in, const int* in_sizes, int n_in,
                              void* d_out, int out_size)
{
    const float* pred = (const float*)d_in[0];
    const float* tbox = (const float*)d_in[1];
    const float* tcls = (const float*)d_in[2];
    const void*  objmap = d_in[3];
    float* out = (float*)d_out;

    const int n_cells = in_sizes[3];                  // N * S * S
    const int n_batch = in_sizes[0] / (14 * 14 * 30);
    int grid = (n_cells + CPB - 1) / CPB;
    if (grid > MAX_GRID) grid = MAX_GRID;             // not reachable at this shape

    yolo_fused_kernel<<<grid, TPB>>>(pred, tbox, tcls, objmap,
                                     n_cells, (float)n_batch, out);
}